// round 10
// baseline (speedup 1.0000x reference)
#include <cuda_runtime.h>
#include <math.h>

// Fixed problem shapes
#define NMAX 100000
#define EMAX 3200000
#define NBMAX 512

// ---------------- scratch (device globals; no allocation allowed) ------------
__device__ int    g_deg[NMAX];
__device__ int    g_off[NMAX];
__device__ int    g_cursor[NMAX];
__device__ int    g_csr_src[EMAX];
__device__ int    g_bsum[NBMAX];
__device__ int    g_bpre[NBMAX];
__device__ float  g_dinv[NMAX];
__device__ __align__(128) uint4 g_msgA[(size_t)NMAX * 8];   // 128B/node max
__device__ __align__(128) uint4 g_msgB[(size_t)NMAX * 8];
__device__ float  g_partial[NBMAX * 16];
__device__ unsigned g_bar_count = 0;
__device__ volatile unsigned g_bar_gen = 0;

// ---------------- packed helpers ---------------------------------------------
__device__ __forceinline__ unsigned long long pack_f32x2(float lo, float hi) {
    unsigned long long r;
    asm("mov.b64 %0, {%1, %2};" : "=l"(r) : "f"(lo), "f"(hi));
    return r;
}
__device__ __forceinline__ void fma_f32x2(unsigned long long& d,
                                          unsigned long long a,
                                          unsigned long long b) {
    asm("fma.rn.f32x2 %0, %1, %2, %0;" : "+l"(d) : "l"(a), "l"(b));
}
__device__ __forceinline__ void unpack_f32x2(float& lo, float& hi, unsigned long long v) {
    asm("mov.b64 {%0, %1}, %2;" : "=f"(lo), "=f"(hi) : "l"(v));
}
__device__ __forceinline__ unsigned cvt_bf16x2(float lo, float hi) {
    unsigned r;
    asm("cvt.rn.bf16x2.f32 %0, %1, %2;" : "=r"(r) : "f"(hi), "f"(lo));
    return r;
}
__device__ __forceinline__ void add_bf2(float& a, float& b, unsigned p) {
    a += __uint_as_float(p << 16);
    b += __uint_as_float(p & 0xffff0000u);
}

// ---------------- software grid barrier ---------------------------------------
// Safe: grid is sized so all blocks are co-resident (launch_bounds(256,2),
// grid = 2*SMs). Generation is read BEFORE arrival; count reset precedes the
// generation flip with a fence; same-thread same-address loads are ordered.
__device__ __forceinline__ void grid_bar(int nb) {
    __syncthreads();
    if (threadIdx.x == 0) {
        unsigned gen = g_bar_gen;
        __threadfence();                 // make this block's writes visible
        if (atomicAdd(&g_bar_count, 1u) == (unsigned)(nb - 1)) {
            atomicExch(&g_bar_count, 0u);
            __threadfence();
            g_bar_gen = gen + 1u;
        } else {
            while (g_bar_gen == gen) { }
        }
    }
    __syncthreads();
}

// Block-wide exclusive scan over 256 values (shuffle + tiny serial).
__device__ __forceinline__ int block_scan_excl(int v, int* sws, int& tot) {
    int lane = threadIdx.x & 31, w = threadIdx.x >> 5;
    int x = v;
#pragma unroll
    for (int off = 1; off < 32; off <<= 1) {
        int y = __shfl_up_sync(0xffffffffu, x, off);
        if (lane >= off) x += y;
    }
    if (lane == 31) sws[w] = x;
    __syncthreads();
    if (threadIdx.x == 0) {
        int run = 0;
#pragma unroll
        for (int i = 0; i < 8; i++) { int t = sws[i]; sws[i] = run; run += t; }
        sws[8] = run;
    }
    __syncthreads();
    tot = sws[8];
    return sws[w] + x - v;
}

// ---------------- the mega kernel ---------------------------------------------
__global__ void __launch_bounds__(256, 2)
mega_kernel(const float* __restrict__ features, const int* __restrict__ ei,
            const float* __restrict__ W1, const float* __restrict__ b1,
            const float* __restrict__ W2, const float* __restrict__ b2,
            const float* __restrict__ W3, const float* __restrict__ b3,
            const float* __restrict__ Wf, const float* __restrict__ bf,
            const float* __restrict__ Ws, const float* __restrict__ bs,
            float* __restrict__ out, int N, int E, int NB)
{
    __shared__ alignas(16) float Wsh[4096];     // 16KB: gemm W staging
    __shared__ alignas(16) float Hsh[2304];     // 9.2KB: per-block h rows
    __shared__ int   sws[9];
    __shared__ float s[256];
    __shared__ float pooled[16], hidden[8], scores[10];

    const int tid = threadIdx.x;
    const int bid = blockIdx.x;
    const int gtid = bid * 256 + tid;
    const int gstride = NB * 256;

    // ---- P0: zero degrees ----
    for (int i = gtid; i < N; i += gstride) __stcg(&g_deg[i], 0);
    grid_bar(NB);

    // ---- P1: count in-degrees ----
    for (int e = gtid; e < E; e += gstride)
        atomicAdd(&g_deg[__ldg(&ei[E + e])], 1);
    grid_bar(NB);

    // ---- P2a: per-block chunk scan (chunk = 512 elements, 2/thread) ----
    {
        int i0 = bid * 512 + 2 * tid, i1 = i0 + 1;
        int a = (i0 < N) ? __ldcg(&g_deg[i0]) : 0;
        int b = (i1 < N) ? __ldcg(&g_deg[i1]) : 0;
        int tot;
        int excl = block_scan_excl(a + b, sws, tot);
        if (i0 < N) g_off[i0] = excl;          // block-relative (same block reads)
        if (i1 < N) g_off[i1] = excl + a;
        if (tid == 0) __stcg(&g_bsum[bid], tot);
    }
    grid_bar(NB);

    // ---- P2b: block 0 scans the NB block totals ----
    if (bid == 0) {
        int i0 = 2 * tid, i1 = i0 + 1;
        int a = (i0 < NB) ? __ldcg(&g_bsum[i0]) : 0;
        int b = (i1 < NB) ? __ldcg(&g_bsum[i1]) : 0;
        int tot;
        int excl = block_scan_excl(a + b, sws, tot);
        if (i0 < NB) __stcg(&g_bpre[i0], excl);
        if (i1 < NB) __stcg(&g_bpre[i1], excl + a);
    }
    grid_bar(NB);

    // ---- P2c: apply prefix; init cursor + dinv ----
    {
        int add = __ldcg(&g_bpre[bid]);
        int i0 = bid * 512 + 2 * tid, i1 = i0 + 1;
        if (i0 < N) {
            int o = g_off[i0] + add;
            __stcg(&g_off[i0], o);
            __stcg(&g_cursor[i0], o);
            __stcg(&g_dinv[i0], rsqrtf((float)__ldcg(&g_deg[i0]) + 1.0f));
        }
        if (i1 < N) {
            int o = g_off[i1] + add;
            __stcg(&g_off[i1], o);
            __stcg(&g_cursor[i1], o);
            __stcg(&g_dinv[i1], rsqrtf((float)__ldcg(&g_deg[i1]) + 1.0f));
        }
    }
    grid_bar(NB);

    // ---- P3: CSR fill ----
    for (int e = gtid; e < E; e += gstride) {
        int sv = __ldg(&ei[e]);
        int d  = __ldg(&ei[E + e]);
        int pos = atomicAdd(&g_cursor[d], 1);
        __stcg(&g_csr_src[pos], sv);
    }
    grid_bar(NB);

    // ---- P4: layer-1 GEMM 256->64, scaled bf16 pack -> msgA ----
    {
        const float4* X4 = (const float4*)features;
        int itersN = (N + gstride - 1) / gstride;
        for (int it = 0; it < itersN; it++) {
            int node = gtid + it * gstride;
            bool v = node < N;
            unsigned long long acc2[32];
#pragma unroll
            for (int j = 0; j < 32; j++) acc2[j] = 0ull;

            for (int k0 = 0; k0 < 256; k0 += 64) {
                __syncthreads();
                for (int i = tid; i < 64 * 64; i += 256)
                    Wsh[i] = __ldg(&W1[k0 * 64 + i]);
                __syncthreads();
                if (v) {
                    for (int kb = 0; kb < 64; kb += 8) {
                        float4 a = X4[(size_t)node * 64 + (size_t)(k0 + kb) / 4];
                        float4 b = X4[(size_t)node * 64 + (size_t)(k0 + kb) / 4 + 1];
                        float xr[8] = {a.x, a.y, a.z, a.w, b.x, b.y, b.z, b.w};
#pragma unroll
                        for (int kk = 0; kk < 8; kk++) {
                            unsigned long long x2 = pack_f32x2(xr[kk], xr[kk]);
                            const ulonglong2* wrow2 =
                                (const ulonglong2*)&Wsh[(kb + kk) * 64];
#pragma unroll
                            for (int j = 0; j < 16; j++) {
                                ulonglong2 w = wrow2[j];
                                fma_f32x2(acc2[2 * j + 0], x2, w.x);
                                fma_f32x2(acc2[2 * j + 1], x2, w.y);
                            }
                        }
                    }
                }
            }
            if (v) {
                float dv = __ldcg(&g_dinv[node]);
#pragma unroll
                for (int q = 0; q < 8; q++) {
                    unsigned r[4];
#pragma unroll
                    for (int t = 0; t < 4; t++) {
                        float lo, hi;
                        unpack_f32x2(lo, hi, acc2[4 * q + t]);
                        r[t] = cvt_bf16x2(lo * dv, hi * dv);
                    }
                    __stcg(&g_msgA[(size_t)node * 8 + q],
                           make_uint4(r[0], r[1], r[2], r[3]));
                }
            }
        }
    }
    grid_bar(NB);

    // ---- P5: agg(64) + GEMM 64->32  (msgA -> msgB) ----
    {
        for (int i = tid; i < 64 * 32; i += 256) Wsh[i] = __ldg(&W2[i]);
        __syncthreads();
        int lnode = tid >> 3, c = tid & 7;            // CH=8, 32 nodes/block
        int per = NB * 32;
        int iters = (N + per - 1) / per;
        for (int it = 0; it < iters; it++) {
            int node = it * per + bid * 32 + lnode;
            bool v = node < N;
            float acc[8];
#pragma unroll
            for (int u = 0; u < 8; u++) acc[u] = 0.0f;
            if (v) {
                int start = __ldcg(&g_off[node]);
                int end = start + __ldcg(&g_deg[node]);
                uint4 sv = __ldcg(&g_msgA[(size_t)node * 8 + c]);
                add_bf2(acc[0], acc[1], sv.x); add_bf2(acc[2], acc[3], sv.y);
                add_bf2(acc[4], acc[5], sv.z); add_bf2(acc[6], acc[7], sv.w);
                int e = start;
                for (; e + 8 <= end; e += 8) {
                    int sidx[8];
#pragma unroll
                    for (int u = 0; u < 8; u++) sidx[u] = __ldcg(&g_csr_src[e + u]);
                    uint4 vv[8];
#pragma unroll
                    for (int u = 0; u < 8; u++)
                        vv[u] = __ldcg(&g_msgA[(size_t)sidx[u] * 8 + c]);
#pragma unroll
                    for (int u = 0; u < 8; u++) {
                        add_bf2(acc[0], acc[1], vv[u].x); add_bf2(acc[2], acc[3], vv[u].y);
                        add_bf2(acc[4], acc[5], vv[u].z); add_bf2(acc[6], acc[7], vv[u].w);
                    }
                }
                for (; e < end; e++) {
                    uint4 vv = __ldcg(&g_msgA[(size_t)__ldcg(&g_csr_src[e]) * 8 + c]);
                    add_bf2(acc[0], acc[1], vv.x); add_bf2(acc[2], acc[3], vv.y);
                    add_bf2(acc[4], acc[5], vv.z); add_bf2(acc[6], acc[7], vv.w);
                }
                float dv = __ldcg(&g_dinv[node]);
                const float4* b4 = (const float4*)b1;
                float4 bl = b4[c * 2 + 0], bh = b4[c * 2 + 1];
                acc[0] = fmaxf(fmaf(dv, acc[0], bl.x), 0.0f);
                acc[1] = fmaxf(fmaf(dv, acc[1], bl.y), 0.0f);
                acc[2] = fmaxf(fmaf(dv, acc[2], bl.z), 0.0f);
                acc[3] = fmaxf(fmaf(dv, acc[3], bl.w), 0.0f);
                acc[4] = fmaxf(fmaf(dv, acc[4], bh.x), 0.0f);
                acc[5] = fmaxf(fmaf(dv, acc[5], bh.y), 0.0f);
                acc[6] = fmaxf(fmaf(dv, acc[6], bh.z), 0.0f);
                acc[7] = fmaxf(fmaf(dv, acc[7], bh.w), 0.0f);
            }
            float* hrow = &Hsh[lnode * 68];
            *(float4*)&hrow[c * 8 + 0] = make_float4(acc[0], acc[1], acc[2], acc[3]);
            *(float4*)&hrow[c * 8 + 4] = make_float4(acc[4], acc[5], acc[6], acc[7]);
            __syncwarp();
            if (v) {
                unsigned long long a0 = 0ull, a1 = 0ull;
#pragma unroll
                for (int k = 0; k < 64; k += 4) {
                    float4 x4 = *(const float4*)&hrow[k];
                    float xs[4] = {x4.x, x4.y, x4.z, x4.w};
#pragma unroll
                    for (int t = 0; t < 4; t++) {
                        unsigned long long x2 = pack_f32x2(xs[t], xs[t]);
                        ulonglong2 w = *(const ulonglong2*)&Wsh[(k + t) * 32 + c * 4];
                        fma_f32x2(a0, x2, w.x);
                        fma_f32x2(a1, x2, w.y);
                    }
                }
                float dv = __ldcg(&g_dinv[node]);
                float o0, o1, o2, o3;
                unpack_f32x2(o0, o1, a0);
                unpack_f32x2(o2, o3, a1);
                uint2 pk;
                pk.x = cvt_bf16x2(o0 * dv, o1 * dv);
                pk.y = cvt_bf16x2(o2 * dv, o3 * dv);
                __stcg((uint2*)g_msgB + (size_t)node * 8 + c, pk);
            }
            __syncwarp();
        }
    }
    grid_bar(NB);

    // ---- P6: agg(32) + GEMM 32->16  (msgB -> msgA) ----
    {
        __syncthreads();
        for (int i = tid; i < 32 * 16; i += 256) Wsh[i] = __ldg(&W3[i]);
        __syncthreads();
        int lnode = tid >> 2, c = tid & 3;            // CH=4, 64 nodes/block
        int per = NB * 64;
        int iters = (N + per - 1) / per;
        for (int it = 0; it < iters; it++) {
            int node = it * per + bid * 64 + lnode;
            bool v = node < N;
            float acc[8];
#pragma unroll
            for (int u = 0; u < 8; u++) acc[u] = 0.0f;
            if (v) {
                int start = __ldcg(&g_off[node]);
                int end = start + __ldcg(&g_deg[node]);
                uint4 sv = __ldcg(&g_msgB[(size_t)node * 4 + c]);
                add_bf2(acc[0], acc[1], sv.x); add_bf2(acc[2], acc[3], sv.y);
                add_bf2(acc[4], acc[5], sv.z); add_bf2(acc[6], acc[7], sv.w);
                int e = start;
                for (; e + 8 <= end; e += 8) {
                    int sidx[8];
#pragma unroll
                    for (int u = 0; u < 8; u++) sidx[u] = __ldcg(&g_csr_src[e + u]);
                    uint4 vv[8];
#pragma unroll
                    for (int u = 0; u < 8; u++)
                        vv[u] = __ldcg(&g_msgB[(size_t)sidx[u] * 4 + c]);
#pragma unroll
                    for (int u = 0; u < 8; u++) {
                        add_bf2(acc[0], acc[1], vv[u].x); add_bf2(acc[2], acc[3], vv[u].y);
                        add_bf2(acc[4], acc[5], vv[u].z); add_bf2(acc[6], acc[7], vv[u].w);
                    }
                }
                for (; e < end; e++) {
                    uint4 vv = __ldcg(&g_msgB[(size_t)__ldcg(&g_csr_src[e]) * 4 + c]);
                    add_bf2(acc[0], acc[1], vv.x); add_bf2(acc[2], acc[3], vv.y);
                    add_bf2(acc[4], acc[5], vv.z); add_bf2(acc[6], acc[7], vv.w);
                }
                float dv = __ldcg(&g_dinv[node]);
                const float4* b4 = (const float4*)b2;
                float4 bl = b4[c * 2 + 0], bh = b4[c * 2 + 1];
                acc[0] = fmaxf(fmaf(dv, acc[0], bl.x), 0.0f);
                acc[1] = fmaxf(fmaf(dv, acc[1], bl.y), 0.0f);
                acc[2] = fmaxf(fmaf(dv, acc[2], bl.z), 0.0f);
                acc[3] = fmaxf(fmaf(dv, acc[3], bl.w), 0.0f);
                acc[4] = fmaxf(fmaf(dv, acc[4], bh.x), 0.0f);
                acc[5] = fmaxf(fmaf(dv, acc[5], bh.y), 0.0f);
                acc[6] = fmaxf(fmaf(dv, acc[6], bh.z), 0.0f);
                acc[7] = fmaxf(fmaf(dv, acc[7], bh.w), 0.0f);
            }
            float* hrow = &Hsh[lnode * 36];
            *(float4*)&hrow[c * 8 + 0] = make_float4(acc[0], acc[1], acc[2], acc[3]);
            *(float4*)&hrow[c * 8 + 4] = make_float4(acc[4], acc[5], acc[6], acc[7]);
            __syncwarp();
            if (v) {
                unsigned long long a0 = 0ull, a1 = 0ull;
#pragma unroll
                for (int k = 0; k < 32; k += 4) {
                    float4 x4 = *(const float4*)&hrow[k];
                    float xs[4] = {x4.x, x4.y, x4.z, x4.w};
#pragma unroll
                    for (int t = 0; t < 4; t++) {
                        unsigned long long x2 = pack_f32x2(xs[t], xs[t]);
                        ulonglong2 w = *(const ulonglong2*)&Wsh[(k + t) * 16 + c * 4];
                        fma_f32x2(a0, x2, w.x);
                        fma_f32x2(a1, x2, w.y);
                    }
                }
                float dv = __ldcg(&g_dinv[node]);
                float o0, o1, o2, o3;
                unpack_f32x2(o0, o1, a0);
                unpack_f32x2(o2, o3, a1);
                uint2 pk;
                pk.x = cvt_bf16x2(o0 * dv, o1 * dv);
                pk.y = cvt_bf16x2(o2 * dv, o3 * dv);
                __stcg((uint2*)g_msgA + (size_t)node * 4 + c, pk);
            }
            __syncwarp();
        }
    }
    grid_bar(NB);

    // ---- P7: agg(16) + pooling partials (reads msgA) ----
    {
        int lnode = tid >> 1, c = tid & 1;            // CH=2, 128 nodes/block
        int f = tid & 15, grp = tid >> 4;
        int per = NB * 128;
        int iters = (N + per - 1) / per;
        float psum = 0.0f;
        for (int it = 0; it < iters; it++) {
            int node = it * per + bid * 128 + lnode;
            bool v = node < N;
            float acc[8];
#pragma unroll
            for (int u = 0; u < 8; u++) acc[u] = 0.0f;
            if (v) {
                int start = __ldcg(&g_off[node]);
                int end = start + __ldcg(&g_deg[node]);
                uint4 sv = __ldcg(&g_msgA[(size_t)node * 2 + c]);
                add_bf2(acc[0], acc[1], sv.x); add_bf2(acc[2], acc[3], sv.y);
                add_bf2(acc[4], acc[5], sv.z); add_bf2(acc[6], acc[7], sv.w);
                int e = start;
                for (; e + 8 <= end; e += 8) {
                    int sidx[8];
#pragma unroll
                    for (int u = 0; u < 8; u++) sidx[u] = __ldcg(&g_csr_src[e + u]);
                    uint4 vv[8];
#pragma unroll
                    for (int u = 0; u < 8; u++)
                        vv[u] = __ldcg(&g_msgA[(size_t)sidx[u] * 2 + c]);
#pragma unroll
                    for (int u = 0; u < 8; u++) {
                        add_bf2(acc[0], acc[1], vv[u].x); add_bf2(acc[2], acc[3], vv[u].y);
                        add_bf2(acc[4], acc[5], vv[u].z); add_bf2(acc[6], acc[7], vv[u].w);
                    }
                }
                for (; e < end; e++) {
                    uint4 vv = __ldcg(&g_msgA[(size_t)__ldcg(&g_csr_src[e]) * 2 + c]);
                    add_bf2(acc[0], acc[1], vv.x); add_bf2(acc[2], acc[3], vv.y);
                    add_bf2(acc[4], acc[5], vv.z); add_bf2(acc[6], acc[7], vv.w);
                }
                float dv = __ldcg(&g_dinv[node]);
                const float4* b4 = (const float4*)b3;
                float4 bl = b4[c * 2 + 0], bh = b4[c * 2 + 1];
                acc[0] = fmaxf(fmaf(dv, acc[0], bl.x), 0.0f);
                acc[1] = fmaxf(fmaf(dv, acc[1], bl.y), 0.0f);
                acc[2] = fmaxf(fmaf(dv, acc[2], bl.z), 0.0f);
                acc[3] = fmaxf(fmaf(dv, acc[3], bl.w), 0.0f);
                acc[4] = fmaxf(fmaf(dv, acc[4], bh.x), 0.0f);
                acc[5] = fmaxf(fmaf(dv, acc[5], bh.y), 0.0f);
                acc[6] = fmaxf(fmaf(dv, acc[6], bh.z), 0.0f);
                acc[7] = fmaxf(fmaf(dv, acc[7], bh.w), 0.0f);
            }
            float* hrow = &Hsh[lnode * 16];
            *(float4*)&hrow[c * 8 + 0] = make_float4(acc[0], acc[1], acc[2], acc[3]);
            *(float4*)&hrow[c * 8 + 4] = make_float4(acc[4], acc[5], acc[6], acc[7]);
            __syncthreads();
#pragma unroll
            for (int u = 0; u < 8; u++)
                psum += Hsh[(grp + u * 16) * 16 + f];
            __syncthreads();
        }
        s[tid] = psum;
        __syncthreads();
        for (int off = 128; off >= 16; off >>= 1) {
            if (tid < off) s[tid] += s[tid + off];
            __syncthreads();
        }
        if (tid < 16) __stcg(&g_partial[bid * 16 + tid], s[tid]);
    }
    grid_bar(NB);

    // ---- P8: head (block 0) ----
    if (bid == 0) {
        if (tid < 16) {
            float sum = 0.0f;
            for (int b = 0; b < NB; b++) sum += __ldcg(&g_partial[b * 16 + tid]);
            pooled[tid] = sum / (float)N;
        }
        __syncthreads();
        if (tid < 8) {
            float a = __ldg(&bf[tid]);
            for (int k = 0; k < 16; k++) a = fmaf(pooled[k], __ldg(&Wf[k * 8 + tid]), a);
            hidden[tid] = fmaxf(a, 0.0f);
        }
        __syncthreads();
        if (tid < 10) {
            float a = __ldg(&bs[tid]);
            for (int k = 0; k < 8; k++) a = fmaf(hidden[k], __ldg(&Ws[k * 10 + tid]), a);
            scores[tid] = a;
        }
        __syncthreads();
        if (tid == 0) {
            float m = scores[0];
            for (int j = 1; j < 10; j++) m = fmaxf(m, scores[j]);
            float sum = 0.0f;
            for (int j = 0; j < 10; j++) sum += expf(scores[j] - m);
            float lse = m + logf(sum);
            for (int j = 0; j < 10; j++) out[j] = scores[j] - lse;
        }
    }
}

// ---------------- launch ------------------------------------------------------
extern "C" void kernel_launch(void* const* d_in, const int* in_sizes, int n_in,
                              void* d_out, int out_size) {
    const float* features = (const float*)d_in[0];
    const int*   ei       = (const int*)d_in[1];   // int32 (JAX default int width)
    const float* W1 = (const float*)d_in[2];  const float* b1 = (const float*)d_in[3];
    const float* W2 = (const float*)d_in[4];  const float* b2 = (const float*)d_in[5];
    const float* W3 = (const float*)d_in[6];  const float* b3 = (const float*)d_in[7];
    const float* Wf = (const float*)d_in[8];  const float* bf = (const float*)d_in[9];
    const float* Ws = (const float*)d_in[10]; const float* bs = (const float*)d_in[11];

    int N = in_sizes[0] / 256;
    int E = in_sizes[1] / 2;

    int dev = 0;
    cudaGetDevice(&dev);
    int sms = 148;
    cudaDeviceGetAttribute(&sms, cudaDevAttrMultiProcessorCount, dev);
    int NB = sms * 2;                       // guaranteed resident via launch_bounds(256,2)
    if (NB > NBMAX) NB = NBMAX;
    // chunked scan assumes NB*512 >= N (N=100k, NB>=196 on any full-die part)

    mega_kernel<<<NB, 256>>>(features, ei, W1, b1, W2, b2, W3, b3,
                             Wf, bf, Ws, bs, (float*)d_out, N, E, NB);
}

// round 11
// speedup vs baseline: 1.1036x; 1.1036x over previous
#include <cuda_runtime.h>
#include <math.h>

// Problem constants (fixed shapes for this problem)
#define NMAX 100000
#define EMAX 3200000
#define SCAN_B 1024

// ---------------- scratch (device globals; no allocation allowed) ------------
__device__ int    g_deg[NMAX];                       // in-degree (int)
__device__ int    g_off[NMAX];                       // CSR exclusive offsets
__device__ int    g_cursor[NMAX];                    // fill cursors
__device__ int    g_csr_src[EMAX];                   // src ids, grouped by dst
__device__ int    g_blocksum[128];                   // scan partials
__device__ float  g_dinv[NMAX];                      // rsqrt(deg+1)
// Double-buffered bf16 message arrays (gather input vs GEMM output must be
// distinct buffers: cross-block race otherwise).
__device__ uint4  g_msgA[(size_t)NMAX * 8];          // 8 uint4 = 64 bf16 / node
__device__ uint4  g_msgB[(size_t)NMAX * 8];
__device__ float  g_partial[16384];                  // pooling partials

// ---------------- packed helpers ---------------------------------------------
__device__ __forceinline__ unsigned long long pack_f32x2(float lo, float hi) {
    unsigned long long r;
    asm("mov.b64 %0, {%1, %2};" : "=l"(r) : "f"(lo), "f"(hi));
    return r;
}
__device__ __forceinline__ void fma_f32x2(unsigned long long& d,
                                          unsigned long long a,
                                          unsigned long long b) {
    asm("fma.rn.f32x2 %0, %1, %2, %0;" : "+l"(d) : "l"(a), "l"(b));
}
__device__ __forceinline__ void unpack_f32x2(float& lo, float& hi, unsigned long long v) {
    asm("mov.b64 {%0, %1}, %2;" : "=f"(lo), "=f"(hi) : "l"(v));
}
__device__ __forceinline__ unsigned cvt_bf16x2(float lo, float hi) {
    unsigned r;
    asm("cvt.rn.bf16x2.f32 %0, %1, %2;" : "=r"(r) : "f"(hi), "f"(lo));
    return r;
}
__device__ __forceinline__ void add_bf2(float& a, float& b, unsigned p) {
    a += __uint_as_float(p << 16);
    b += __uint_as_float(p & 0xffff0000u);
}

// ---------------- degree / CSR construction ----------------------------------
__global__ void zero_deg_kernel(int n) {
    int i = blockIdx.x * 256 + threadIdx.x;
    if (i < n) g_deg[i] = 0;
}

__global__ void deg_count_kernel(const int* __restrict__ ei, int E) {
    int e = blockIdx.x * 256 + threadIdx.x;
    if (e < E) atomicAdd(&g_deg[ei[E + e]], 1);
}

// Shuffle-based block exclusive scan of g_deg -> g_off (+ dinv fold-in).
__global__ void scan1_kernel(int n) {
    __shared__ int warpsum[32];
    int i = blockIdx.x * SCAN_B + threadIdx.x;
    int v = (i < n) ? g_deg[i] : 0;
    if (i < n) g_dinv[i] = rsqrtf((float)v + 1.0f);
    int lane = threadIdx.x & 31;
    int wid = threadIdx.x >> 5;
    int x = v;
#pragma unroll
    for (int off = 1; off < 32; off <<= 1) {
        int y = __shfl_up_sync(0xffffffffu, x, off);
        if (lane >= off) x += y;
    }
    if (lane == 31) warpsum[wid] = x;
    __syncthreads();
    if (wid == 0) {
        int s = warpsum[lane];
#pragma unroll
        for (int off = 1; off < 32; off <<= 1) {
            int y = __shfl_up_sync(0xffffffffu, s, off);
            if (lane >= off) s += y;
        }
        warpsum[lane] = s;
    }
    __syncthreads();
    int base = (wid > 0) ? warpsum[wid - 1] : 0;
    int incl = base + x;
    if (i < n) g_off[i] = incl - v;                  // exclusive within block
    if (threadIdx.x == SCAN_B - 1) g_blocksum[blockIdx.x] = incl;
}

// Merged scan2+scan3: every block redundantly scans the <=128 block totals
// (shuffle scan over 4 warps), then applies its prefix.
__global__ void scan23_kernel(int n, int nb) {
    __shared__ int ws[4];
    __shared__ int incl128[128];
    int t = threadIdx.x;
    if (t < 128) {
        int lane = t & 31;
        int w = t >> 5;
        int s = (t < nb) ? g_blocksum[t] : 0;
#pragma unroll
        for (int off = 1; off < 32; off <<= 1) {
            int y = __shfl_up_sync(0xffffffffu, s, off);
            if (lane >= off) s += y;
        }
        if (lane == 31) ws[w] = s;
        incl128[t] = s;
    }
    __syncthreads();
    if (t < 128) {
        int w = t >> 5;
        int add = 0;
        for (int u = 0; u < w; u++) add += ws[u];
        incl128[t] += add;
    }
    __syncthreads();
    int add = (blockIdx.x == 0) ? 0 : incl128[blockIdx.x - 1];
    int i = blockIdx.x * SCAN_B + t;
    if (i < n) {
        int o = g_off[i] + add;
        g_off[i] = o;
        g_cursor[i] = o;
    }
}

__global__ void csr_fill_kernel(const int* __restrict__ ei, int E) {
    int e = blockIdx.x * 256 + threadIdx.x;
    if (e < E) {
        int s = ei[e];
        int d = ei[E + e];
        int pos = atomicAdd(&g_cursor[d], 1);
        g_csr_src[pos] = s;
    }
}

// ---------------- layer-1 GEMM: tiled, 2 nodes/thread -------------------------
// msgA[node,:] = bf16((X[node,:] @ W) * dinv[node])
// Block = 128 threads, tile = 256 nodes. X staged through smem:
//  - global loads are full-128B-line coalesced (8 lanes x 16B per row chunk)
//  - smem rows padded to stride 33 -> conflict-free scalar reads
// Each thread owns 2 nodes, so each broadcast W-LDS feeds 4 packed FMAs.
// K=256, NOUT=64, KC=32.
__global__ void __launch_bounds__(128)
gemm_scaled_kernel(const float* __restrict__ X, const float* __restrict__ W, int n) {
    constexpr int K = 256, NOUT = 64, KC = 32, TS = 33;
    __shared__ float Xs[256 * TS];                  // 33.8 KB
    __shared__ alignas(16) float Wsh[KC * NOUT];    // 8 KB

    const float4* X4 = (const float4*)X;
    int t = threadIdx.x;
    int base = blockIdx.x * 256;
    int n0 = base + t, n1 = base + t + 128;
    bool v0 = n0 < n, v1 = n1 < n;

    unsigned long long acc0[NOUT / 2], acc1[NOUT / 2];
#pragma unroll
    for (int j = 0; j < NOUT / 2; j++) { acc0[j] = 0ull; acc1[j] = 0ull; }

    for (int k0 = 0; k0 < K; k0 += KC) {
        __syncthreads();
        // stage W chunk (2048 floats, 16/thread)
        for (int i = t; i < KC * NOUT; i += 128)
            Wsh[i] = W[k0 * NOUT + i];
        // stage X tile: 256 rows x KC floats = 2048 float4, 16/thread.
        // flat f: row = f>>3 (8 float4 per row-chunk), lanes 0-7 cover one
        // full 128B line -> 4 full-line wavefronts per warp instruction.
        for (int f = t; f < 256 * (KC / 4); f += 128) {
            int row = f >> 3;
            int c4 = f & 7;
            float4 val = make_float4(0.f, 0.f, 0.f, 0.f);
            if (base + row < n)
                val = X4[(size_t)(base + row) * (K / 4) + k0 / 4 + c4];
            float* dst = &Xs[row * TS + c4 * 4];
            dst[0] = val.x; dst[1] = val.y; dst[2] = val.z; dst[3] = val.w;
        }
        __syncthreads();

        for (int kk = 0; kk < KC; kk++) {
            float x0 = Xs[t * TS + kk];
            float x1 = Xs[(t + 128) * TS + kk];
            unsigned long long p0 = pack_f32x2(x0, x0);
            unsigned long long p1 = pack_f32x2(x1, x1);
            const ulonglong2* wrow2 = (const ulonglong2*)&Wsh[kk * NOUT];
#pragma unroll
            for (int j = 0; j < NOUT / 4; j++) {
                ulonglong2 w = wrow2[j];            // one broadcast LDS.128 ...
                fma_f32x2(acc0[2 * j + 0], p0, w.x);  // ... feeds 4 packed FMAs
                fma_f32x2(acc0[2 * j + 1], p0, w.y);
                fma_f32x2(acc1[2 * j + 0], p1, w.x);
                fma_f32x2(acc1[2 * j + 1], p1, w.y);
            }
        }
    }

    if (v0) {
        float dv = g_dinv[n0];
#pragma unroll
        for (int q = 0; q < NOUT / 8; q++) {
            unsigned r[4];
#pragma unroll
            for (int u = 0; u < 4; u++) {
                float lo, hi;
                unpack_f32x2(lo, hi, acc0[4 * q + u]);
                r[u] = cvt_bf16x2(lo * dv, hi * dv);
            }
            g_msgA[(size_t)n0 * 8 + q] = make_uint4(r[0], r[1], r[2], r[3]);
        }
    }
    if (v1) {
        float dv = g_dinv[n1];
#pragma unroll
        for (int q = 0; q < NOUT / 8; q++) {
            unsigned r[4];
#pragma unroll
            for (int u = 0; u < 4; u++) {
                float lo, hi;
                unpack_f32x2(lo, hi, acc1[4 * q + u]);
                r[u] = cvt_bf16x2(lo * dv, hi * dv);
            }
            g_msgA[(size_t)n1 * 8 + q] = make_uint4(r[0], r[1], r[2], r[3]);
        }
    }
}

// ---------------- fused aggregate + next-layer GEMM (warp-autonomous) ---------
// Phase A: h = relu(dinv*(gather-sum(in) + self) + bias)  -> per-warp smem rows
// Phase B: out = bf16((h @ W) * dinv)                      (f32x2 from smem)
// dir=0: in=msgA out=msgB ; dir=1: in=msgB out=msgA
template <int NIN, int NOUT>
__global__ void fused_agg_gemm_kernel(const float* __restrict__ bias,
                                      const float* __restrict__ W,
                                      int n, int dir) {
    constexpr int CH = NIN / 8;                  // lanes per node (agg phase)
    constexpr int NPB = 256 / CH;                // nodes per block
    constexpr int HS = NIN + 4;                  // padded h row (floats)
    __shared__ alignas(16) float Wsh[NIN * NOUT];
    __shared__ alignas(16) float Hsh[NPB * HS];

    const uint4* __restrict__ msg_in  = dir ? g_msgB : g_msgA;
    uint2* __restrict__       msg_out = dir ? (uint2*)g_msgA : (uint2*)g_msgB;

    int lnode = threadIdx.x / CH;
    int c = threadIdx.x % CH;
    int node = blockIdx.x * NPB + lnode;
    bool valid = node < n;

    for (int i = threadIdx.x; i < NIN * NOUT; i += 256) Wsh[i] = W[i];
    __syncthreads();   // Wsh ready BEFORE divergent gather; no barrier after

    // ---- Phase A: aggregate ----
    float acc[8];
#pragma unroll
    for (int u = 0; u < 8; u++) acc[u] = 0.0f;

    if (valid) {
        int start = g_off[node];
        int end = start + g_deg[node];
        {
            uint4 sv = msg_in[(size_t)node * CH + c];   // self-loop
            add_bf2(acc[0], acc[1], sv.x);
            add_bf2(acc[2], acc[3], sv.y);
            add_bf2(acc[4], acc[5], sv.z);
            add_bf2(acc[6], acc[7], sv.w);
        }
        int e = start;
        for (; e + 8 <= end; e += 8) {
            int sidx[8];
#pragma unroll
            for (int u = 0; u < 8; u++) sidx[u] = g_csr_src[e + u];
            uint4 v[8];
#pragma unroll
            for (int u = 0; u < 8; u++) v[u] = msg_in[(size_t)sidx[u] * CH + c];
#pragma unroll
            for (int u = 0; u < 8; u++) {
                add_bf2(acc[0], acc[1], v[u].x);
                add_bf2(acc[2], acc[3], v[u].y);
                add_bf2(acc[4], acc[5], v[u].z);
                add_bf2(acc[6], acc[7], v[u].w);
            }
        }
        for (; e < end; e++) {
            uint4 v = msg_in[(size_t)g_csr_src[e] * CH + c];
            add_bf2(acc[0], acc[1], v.x);
            add_bf2(acc[2], acc[3], v.y);
            add_bf2(acc[4], acc[5], v.z);
            add_bf2(acc[6], acc[7], v.w);
        }
        float dv = g_dinv[node];
        const float4* b4 = (const float4*)bias;
        float4 bl = b4[c * 2 + 0];
        float4 bh = b4[c * 2 + 1];
        acc[0] = fmaxf(fmaf(dv, acc[0], bl.x), 0.0f);
        acc[1] = fmaxf(fmaf(dv, acc[1], bl.y), 0.0f);
        acc[2] = fmaxf(fmaf(dv, acc[2], bl.z), 0.0f);
        acc[3] = fmaxf(fmaf(dv, acc[3], bl.w), 0.0f);
        acc[4] = fmaxf(fmaf(dv, acc[4], bh.x), 0.0f);
        acc[5] = fmaxf(fmaf(dv, acc[5], bh.y), 0.0f);
        acc[6] = fmaxf(fmaf(dv, acc[6], bh.z), 0.0f);
        acc[7] = fmaxf(fmaf(dv, acc[7], bh.w), 0.0f);
    }
    float* hrow = &Hsh[lnode * HS];
    *(float4*)&hrow[c * 8 + 0] = make_float4(acc[0], acc[1], acc[2], acc[3]);
    *(float4*)&hrow[c * 8 + 4] = make_float4(acc[4], acc[5], acc[6], acc[7]);
    __syncwarp();      // h rows for this warp's nodes are warp-local

    // ---- Phase B: GEMM from smem; each lane computes NOUT/CH = 4 outputs ----
    if (valid) {
        unsigned long long a0 = 0ull, a1 = 0ull;         // outputs c*4..c*4+3
#pragma unroll
        for (int k = 0; k < NIN; k += 4) {
            float4 x4 = *(const float4*)&hrow[k];
            float xs[4] = {x4.x, x4.y, x4.z, x4.w};
#pragma unroll
            for (int t = 0; t < 4; t++) {
                unsigned long long x2 = pack_f32x2(xs[t], xs[t]);
                ulonglong2 w = *(const ulonglong2*)&Wsh[(k + t) * NOUT + c * 4];
                fma_f32x2(a0, x2, w.x);
                fma_f32x2(a1, x2, w.y);
            }
        }
        float dv = g_dinv[node];
        float o0, o1, o2, o3;
        unpack_f32x2(o0, o1, a0);
        unpack_f32x2(o2, o3, a1);
        uint2 pk;
        pk.x = cvt_bf16x2(o0 * dv, o1 * dv);
        pk.y = cvt_bf16x2(o2 * dv, o3 * dv);
        msg_out[(size_t)node * (NOUT / 4) + c] = pk;
    }
}

// ---------------- fused aggregate (16 feats) + block pooling ------------------
// Reads msgA (written by the second fused kernel). No write to msg buffers.
__global__ void fused_agg_pool_kernel(const float* __restrict__ bias, int n) {
    constexpr int CH = 2, NPB = 128, HS = 16;
    __shared__ float Hsh[NPB * HS];
    __shared__ float s[256];

    int lnode = threadIdx.x / CH;
    int c = threadIdx.x % CH;
    int node = blockIdx.x * NPB + lnode;
    bool valid = node < n;

    float acc[8];
#pragma unroll
    for (int u = 0; u < 8; u++) acc[u] = 0.0f;

    if (valid) {
        int start = g_off[node];
        int end = start + g_deg[node];
        {
            uint4 sv = g_msgA[(size_t)node * CH + c];
            add_bf2(acc[0], acc[1], sv.x);
            add_bf2(acc[2], acc[3], sv.y);
            add_bf2(acc[4], acc[5], sv.z);
            add_bf2(acc[6], acc[7], sv.w);
        }
        int e = start;
        for (; e + 8 <= end; e += 8) {
            int sidx[8];
#pragma unroll
            for (int u = 0; u < 8; u++) sidx[u] = g_csr_src[e + u];
            uint4 v[8];
#pragma unroll
            for (int u = 0; u < 8; u++) v[u] = g_msgA[(size_t)sidx[u] * CH + c];
#pragma unroll
            for (int u = 0; u < 8; u++) {
                add_bf2(acc[0], acc[1], v[u].x);
                add_bf2(acc[2], acc[3], v[u].y);
                add_bf2(acc[4], acc[5], v[u].z);
                add_bf2(acc[6], acc[7], v[u].w);
            }
        }
        for (; e < end; e++) {
            uint4 v = g_msgA[(size_t)g_csr_src[e] * CH + c];
            add_bf2(acc[0], acc[1], v.x);
            add_bf2(acc[2], acc[3], v.y);
            add_bf2(acc[4], acc[5], v.z);
            add_bf2(acc[6], acc[7], v.w);
        }
        float dv = g_dinv[node];
        const float4* b4 = (const float4*)bias;
        float4 bl = b4[c * 2 + 0];
        float4 bh = b4[c * 2 + 1];
        acc[0] = fmaxf(fmaf(dv, acc[0], bl.x), 0.0f);
        acc[1] = fmaxf(fmaf(dv, acc[1], bl.y), 0.0f);
        acc[2] = fmaxf(fmaf(dv, acc[2], bl.z), 0.0f);
        acc[3] = fmaxf(fmaf(dv, acc[3], bl.w), 0.0f);
        acc[4] = fmaxf(fmaf(dv, acc[4], bh.x), 0.0f);
        acc[5] = fmaxf(fmaf(dv, acc[5], bh.y), 0.0f);
        acc[6] = fmaxf(fmaf(dv, acc[6], bh.z), 0.0f);
        acc[7] = fmaxf(fmaf(dv, acc[7], bh.w), 0.0f);
    }
    float* hrow = &Hsh[lnode * HS];
    *(float4*)&hrow[c * 8 + 0] = make_float4(acc[0], acc[1], acc[2], acc[3]);
    *(float4*)&hrow[c * 8 + 4] = make_float4(acc[4], acc[5], acc[6], acc[7]);
    __syncthreads();

    // pooling partial: deterministic block reduction over 128 node rows
    int f = threadIdx.x & 15;
    int grp = threadIdx.x >> 4;
    float sum = 0.0f;
#pragma unroll
    for (int u = 0; u < 8; u++)
        sum += Hsh[(grp + u * 16) * HS + f];
    s[threadIdx.x] = sum;
    __syncthreads();
    for (int off = 128; off >= 16; off >>= 1) {
        if (threadIdx.x < off) s[threadIdx.x] += s[threadIdx.x + off];
        __syncthreads();
    }
    if (threadIdx.x < 16) g_partial[blockIdx.x * 16 + threadIdx.x] = s[threadIdx.x];
}

// ---------------- final head --------------------------------------------------
__global__ void final_mlp_kernel(const float* __restrict__ Wf, const float* __restrict__ bf,
                                 const float* __restrict__ Ws, const float* __restrict__ bs,
                                 float* __restrict__ out, int n, int nblocks) {
    __shared__ float pooled[16];
    __shared__ float hidden[8];
    __shared__ float scores[10];
    int t = threadIdx.x;   // 32 threads
    if (t < 16) {
        float sum = 0.0f;
        for (int b = 0; b < nblocks; b++) sum += g_partial[b * 16 + t];
        pooled[t] = sum / (float)n;
    }
    __syncthreads();
    if (t < 8) {
        float a = bf[t];
        for (int k = 0; k < 16; k++) a = fmaf(pooled[k], Wf[k * 8 + t], a);
        hidden[t] = fmaxf(a, 0.0f);
    }
    __syncthreads();
    if (t < 10) {
        float a = bs[t];
        for (int k = 0; k < 8; k++) a = fmaf(hidden[k], Ws[k * 10 + t], a);
        scores[t] = a;
    }
    __syncthreads();
    if (t == 0) {
        float m = scores[0];
        for (int j = 1; j < 10; j++) m = fmaxf(m, scores[j]);
        float sum = 0.0f;
        for (int j = 0; j < 10; j++) sum += expf(scores[j] - m);
        float lse = m + logf(sum);
        for (int j = 0; j < 10; j++) out[j] = scores[j] - lse;
    }
}

// ---------------- launch ------------------------------------------------------
extern "C" void kernel_launch(void* const* d_in, const int* in_sizes, int n_in,
                              void* d_out, int out_size) {
    const float* features = (const float*)d_in[0];
    const int*   ei       = (const int*)d_in[1];   // int32 (JAX default int width)
    const float* W1 = (const float*)d_in[2];  const float* b1 = (const float*)d_in[3];
    const float* W2 = (const float*)d_in[4];  const float* b2 = (const float*)d_in[5];
    const float* W3 = (const float*)d_in[6];  const float* b3 = (const float*)d_in[7];
    const float* Wf = (const float*)d_in[8];  const float* bf = (const float*)d_in[9];
    const float* Ws = (const float*)d_in[10]; const float* bs = (const float*)d_in[11];

    int N = in_sizes[0] / 256;
    int E = in_sizes[1] / 2;

    int nbN = (N + 255) / 256;
    int nbE = (E + 255) / 256;
    int nbScan = (N + SCAN_B - 1) / SCAN_B;

    // ---- CSR build ----
    zero_deg_kernel<<<nbN, 256>>>(N);
    deg_count_kernel<<<nbE, 256>>>(ei, E);
    scan1_kernel<<<nbScan, SCAN_B>>>(N);
    scan23_kernel<<<nbScan, SCAN_B>>>(N, nbScan);
    csr_fill_kernel<<<nbE, 256>>>(ei, E);

    // ---- layer 1 GEMM: 256 -> 64 (tiled, 2 nodes/thread, writes msgA) ----
    gemm_scaled_kernel<<<(N + 255) / 256, 128>>>(features, W1, N);

    // ---- fused: agg(64) + GEMM 64->32 (msgA -> msgB) ----
    fused_agg_gemm_kernel<64, 32><<<(N + 31) / 32, 256>>>(b1, W2, N, 0);

    // ---- fused: agg(32) + GEMM 32->16 (msgB -> msgA) ----
    fused_agg_gemm_kernel<32, 16><<<(N + 63) / 64, 256>>>(b2, W3, N, 1);

    // ---- fused: agg(16) + pooling partials (reads msgA) ----
    int nbPool = (N + 127) / 128;
    fused_agg_pool_kernel<<<nbPool, 256>>>(b3, N);

    // ---- head ----
    final_mlp_kernel<<<1, 32>>>(Wf, bf, Ws, bs, (float*)d_out, N, nbPool);
}